// round 3
// baseline (speedup 1.0000x reference)
#include <cuda_runtime.h>

// Problem constants (DgaRawSequence: B=256, T=8192, I=6, U=64, M=16)
#define NB 256
#define NT 8192
#define NI 6
#define NU 64
#define NM 16
#define UNFOLDS 6
#define EPSV 1e-8f

__device__ __forceinline__ float tanhf_(float v) {
    float y; asm("tanh.approx.f32 %0, %1;" : "=f"(y) : "f"(v)); return y;
}
__device__ __forceinline__ float rcpf_(float v) {
    float y; asm("rcp.approx.f32 %0, %1;" : "=f"(y) : "f"(v)); return y;
}

// sigmoid(z) = 0.5 + 0.5*tanh(z/2), 0.5's folded into weights.
// Block = 256 threads = 64 u-neurons x 4 j-chunks; ONE block processes TWO
// independent batch elements (b and b+128) with interleaved dependency chains,
// sharing the per-(j,u) parameter registers and the per-unfold barrier.
__global__ void __launch_bounds__(256, 1) ltc_seq_kernel(
    const float* __restrict__ x,
    const float* __restrict__ gleak, const float* __restrict__ vleak,
    const float* __restrict__ cm,
    const float* __restrict__ sigma, const float* __restrict__ mu,
    const float* __restrict__ w,     const float* __restrict__ erev,
    const float* __restrict__ ssigma, const float* __restrict__ smu,
    const float* __restrict__ swv,    const float* __restrict__ serev,
    const float* __restrict__ in_w,  const float* __restrict__ in_b,
    const float* __restrict__ out_w, const float* __restrict__ out_b,
    float* __restrict__ out)
{
    const int tid = threadIdx.x;
    const int u   = tid >> 2;
    const int c   = tid & 3;
    const int bA  = blockIdx.x;          // batch A
    const int bB  = blockIdx.x + 128;    // batch B

    __shared__ __align__(16) float vbuf[2][2][NU];   // [batch][pingpong][u]

    // ---- per-(j,u) recurrent params in registers (shared by both batches) ----
    float p_na[16], p_tb[16], p_wh[16], p_weh[16];
    float denb = 0.f, numb = 0.f;
#pragma unroll
    for (int k = 0; k < 16; k++) {
        int j = c * 16 + k;
        float sg = sigma[j * NU + u];
        float m  = mu[j * NU + u];
        float ww = w[j * NU + u];
        float er = erev[j * NU + u];
        p_na[k]  = 0.5f * sg;
        p_tb[k]  = -0.5f * m * sg;
        p_wh[k]  = 0.5f * ww;
        p_weh[k] = 0.5f * ww * er;
        denb += p_wh[k];
        numb += p_weh[k];
    }

    // ---- sensory params: lane c handles i0=c and i1=c+4 (if < NI) ----
    const int i0 = c;
    const int i1 = c + 4;
    const bool has1 = (i1 < NI);
    float s_na0, s_tb0, s_wh0, s_weh0, iw0, ib0;
    float s_na1 = 0.f, s_tb1 = 0.f, s_wh1 = 0.f, s_weh1 = 0.f, iw1 = 0.f, ib1 = 0.f;
    float s_base_d = 0.f, s_base_n = 0.f;
    {
        float sg = ssigma[i0 * NU + u], m = smu[i0 * NU + u];
        float ww = swv[i0 * NU + u],    er = serev[i0 * NU + u];
        s_na0 = 0.5f * sg; s_tb0 = -0.5f * m * sg;
        s_wh0 = 0.5f * ww; s_weh0 = 0.5f * ww * er;
        s_base_d += s_wh0; s_base_n += s_weh0;
        iw0 = in_w[i0]; ib0 = in_b[i0];
    }
    if (has1) {
        float sg = ssigma[i1 * NU + u], m = smu[i1 * NU + u];
        float ww = swv[i1 * NU + u],    er = serev[i1 * NU + u];
        s_na1 = 0.5f * sg; s_tb1 = -0.5f * m * sg;
        s_wh1 = 0.5f * ww; s_weh1 = 0.5f * ww * er;
        s_base_d += s_wh1; s_base_n += s_weh1;
        iw1 = in_w[i1]; ib1 = in_b[i1];
    }

    // ---- per-u constants ----
    const float cmt  = 6.0f * cm[u];
    const float gl   = gleak[u];
    const float glvl = gl * vleak[u];
    float ow = 0.f, ob = 0.f;
    if (u < NM) { ow = out_w[u]; ob = out_b[u]; }

    // ---- init state v = 0 for both batches ----
    if (tid < NU) { vbuf[0][0][tid] = 0.f; vbuf[1][0][tid] = 0.f; }
    __syncthreads();

    const float* xbA   = x   + (size_t)bA * NT * NI;
    const float* xbB   = x   + (size_t)bB * NT * NI;
    float*       outbA = out + (size_t)bA * NT * NM;
    float*       outbB = out + (size_t)bB * NT * NM;

    // prefetch x for t=0
    float xA0 = xbA[i0], xB0 = xbB[i0];
    float xA1 = has1 ? xbA[i1] : 0.f;
    float xB1 = has1 ? xbB[i1] : 0.f;

    for (int t = 0; t < NT; t++) {
        // ---- sensory sums, both batches interleaved ----
        float dsA, nsA, dsB, nsB;
        {
            float thA0 = tanhf_(fmaf(fmaf(xA0, iw0, ib0), s_na0, s_tb0));
            float thB0 = tanhf_(fmaf(fmaf(xB0, iw0, ib0), s_na0, s_tb0));
            dsA = fmaf(s_wh0,  thA0, s_base_d);
            nsA = fmaf(s_weh0, thA0, s_base_n);
            dsB = fmaf(s_wh0,  thB0, s_base_d);
            nsB = fmaf(s_weh0, thB0, s_base_n);
            if (has1) {
                float thA1 = tanhf_(fmaf(fmaf(xA1, iw1, ib1), s_na1, s_tb1));
                float thB1 = tanhf_(fmaf(fmaf(xB1, iw1, ib1), s_na1, s_tb1));
                dsA = fmaf(s_wh1,  thA1, dsA);
                nsA = fmaf(s_weh1, thA1, nsA);
                dsB = fmaf(s_wh1,  thB1, dsB);
                nsB = fmaf(s_weh1, thB1, nsB);
            }
        }
        nsA += __shfl_xor_sync(0xffffffffu, nsA, 1);
        dsA += __shfl_xor_sync(0xffffffffu, dsA, 1);
        nsB += __shfl_xor_sync(0xffffffffu, nsB, 1);
        dsB += __shfl_xor_sync(0xffffffffu, dsB, 1);
        nsA += __shfl_xor_sync(0xffffffffu, nsA, 2);
        dsA += __shfl_xor_sync(0xffffffffu, dsA, 2);
        nsB += __shfl_xor_sync(0xffffffffu, nsB, 2);
        dsB += __shfl_xor_sync(0xffffffffu, dsB, 2);

        // ---- prefetch next timestep's x ----
        if (t + 1 < NT) {
            xA0 = xbA[(t + 1) * NI + i0];
            xB0 = xbB[(t + 1) * NI + i0];
            if (has1) {
                xA1 = xbA[(t + 1) * NI + i1];
                xB1 = xbB[(t + 1) * NI + i1];
            }
        }

        float vlastA = 0.f, vlastB = 0.f;
#pragma unroll
        for (int s = 0; s < UNFOLDS; s++) {
            const int rb = s & 1;
            const float* vpA = vbuf[0][rb];
            const float* vpB = vbuf[1][rb];

            const float4* vpA4 = (const float4*)(vpA + c * 16);
            const float4* vpB4 = (const float4*)(vpB + c * 16);

            float denA0 = denb, numA0 = numb, denA1 = 0.f, numA1 = 0.f;
            float denB0 = denb, numB0 = numb, denB1 = 0.f, numB1 = 0.f;

#pragma unroll
            for (int q = 0; q < 4; q++) {
                float4 qa = vpA4[q];
                float4 qb = vpB4[q];
                float va[4] = {qa.x, qa.y, qa.z, qa.w};
                float vb[4] = {qb.x, qb.y, qb.z, qb.w};
#pragma unroll
                for (int r = 0; r < 4; r++) {
                    const int k = q * 4 + r;
                    float thA = tanhf_(fmaf(va[r], p_na[k], p_tb[k]));
                    float thB = tanhf_(fmaf(vb[r], p_na[k], p_tb[k]));
                    if (k & 1) {
                        denA1 = fmaf(p_wh[k],  thA, denA1);
                        numA1 = fmaf(p_weh[k], thA, numA1);
                        denB1 = fmaf(p_wh[k],  thB, denB1);
                        numB1 = fmaf(p_weh[k], thB, numB1);
                    } else {
                        denA0 = fmaf(p_wh[k],  thA, denA0);
                        numA0 = fmaf(p_weh[k], thA, numA0);
                        denB0 = fmaf(p_wh[k],  thB, denB0);
                        numB0 = fmaf(p_weh[k], thB, numB0);
                    }
                }
            }
            float numA = numA0 + numA1, denA = denA0 + denA1;
            float numB = numB0 + numB1, denB = denB0 + denB1;
            numA += __shfl_xor_sync(0xffffffffu, numA, 1);
            denA += __shfl_xor_sync(0xffffffffu, denA, 1);
            numB += __shfl_xor_sync(0xffffffffu, numB, 1);
            denB += __shfl_xor_sync(0xffffffffu, denB, 1);
            numA += __shfl_xor_sync(0xffffffffu, numA, 2);
            denA += __shfl_xor_sync(0xffffffffu, denA, 2);
            numB += __shfl_xor_sync(0xffffffffu, numB, 2);
            denB += __shfl_xor_sync(0xffffffffu, denB, 2);

            if (c == 0) {
                float vuA = vpA[u];
                float vuB = vpB[u];
                float nnA = fmaf(cmt, vuA, glvl) + numA + nsA;
                float ddA = cmt + gl + denA + dsA + EPSV;
                float nnB = fmaf(cmt, vuB, glvl) + numB + nsB;
                float ddB = cmt + gl + denB + dsB + EPSV;
                float vnA = nnA * rcpf_(ddA);
                float vnB = nnB * rcpf_(ddB);
                vbuf[0][rb ^ 1][u] = vnA;
                vbuf[1][rb ^ 1][u] = vnB;
                vlastA = vnA;
                vlastB = vnB;
            }
            __syncthreads();
        }

        // ---- output: first M motor neurons, affine, both batches ----
        if (c == 0 && u < NM) {
            outbA[t * NM + u] = fmaf(vlastA, ow, ob);
            outbB[t * NM + u] = fmaf(vlastB, ow, ob);
        }
    }
}

extern "C" void kernel_launch(void* const* d_in, const int* in_sizes, int n_in,
                              void* d_out, int out_size) {
    (void)in_sizes; (void)n_in; (void)out_size;
    const float* xx     = (const float*)d_in[0];
    const float* gleak  = (const float*)d_in[1];
    const float* vleak  = (const float*)d_in[2];
    const float* cm     = (const float*)d_in[3];
    const float* sigma  = (const float*)d_in[4];
    const float* mu     = (const float*)d_in[5];
    const float* w      = (const float*)d_in[6];
    const float* erev   = (const float*)d_in[7];
    const float* ssig   = (const float*)d_in[8];
    const float* smu    = (const float*)d_in[9];
    const float* sw     = (const float*)d_in[10];
    const float* serev  = (const float*)d_in[11];
    const float* in_w   = (const float*)d_in[12];
    const float* in_b   = (const float*)d_in[13];
    const float* out_w  = (const float*)d_in[14];
    const float* out_b  = (const float*)d_in[15];
    float* out = (float*)d_out;

    ltc_seq_kernel<<<NB / 2, 256>>>(xx, gleak, vleak, cm, sigma, mu, w, erev,
                                    ssig, smu, sw, serev, in_w, in_b, out_w, out_b,
                                    out);
}

// round 5
// speedup vs baseline: 1.5918x; 1.5918x over previous
#include <cuda_runtime.h>

// Problem constants (DgaRawSequence: B=256, T=8192, I=6, U=64, M=16)
#define NB 256
#define NT 8192
#define NI 6
#define NU 64
#define NM 16
#define UNFOLDS 6
#define EPSV 1e-8f

__device__ __forceinline__ float tanhf_(float v) {
    float y; asm("tanh.approx.f32 %0, %1;" : "=f"(y) : "f"(v)); return y;
}
__device__ __forceinline__ float rcpf_(float v) {
    float y; asm("rcp.approx.f32 %0, %1;" : "=f"(y) : "f"(v)); return y;
}

// sigmoid(z) = 0.5 + 0.5*tanh(z/2), 0.5's folded into weights.
// Block = 128 threads = 64 u-neurons x 2 j-chunks (32 presynaptic j each).
// tid = u*2 + c ; the two lanes of one u are adjacent -> shfl.xor(1) reduces over c.
// One block per batch element (grid=256 -> 2 blocks/SM co-resident to hide the
// per-unfold barrier tail). v(u) is carried in a register (computed redundantly
// in both c-lanes), so only the 32 vj values are read from shared per unfold.
__global__ void __launch_bounds__(128, 2) ltc_seq_kernel(
    const float* __restrict__ x,
    const float* __restrict__ gleak, const float* __restrict__ vleak,
    const float* __restrict__ cm,
    const float* __restrict__ sigma, const float* __restrict__ mu,
    const float* __restrict__ w,     const float* __restrict__ erev,
    const float* __restrict__ ssigma, const float* __restrict__ smu,
    const float* __restrict__ swv,    const float* __restrict__ serev,
    const float* __restrict__ in_w,  const float* __restrict__ in_b,
    const float* __restrict__ out_w, const float* __restrict__ out_b,
    float* __restrict__ out)
{
    const int tid = threadIdx.x;
    const int u   = tid >> 1;
    const int c   = tid & 1;
    const int b   = blockIdx.x;

    __shared__ __align__(16) float vbuf[2][NU];

    // ---- per-(j,u) recurrent params in registers, j = 32*c + k ----
    float p_na[32], p_tb[32], p_wh[32], p_weh[32];
    float denb = 0.f, numb = 0.f;   // sum of (w/2), (w*erev/2) bases
#pragma unroll
    for (int k = 0; k < 32; k++) {
        int j = c * 32 + k;
        float sg = sigma[j * NU + u];
        float m  = mu[j * NU + u];
        float ww = w[j * NU + u];
        float er = erev[j * NU + u];
        p_na[k]  = 0.5f * sg;            // multiplies v (z/2)
        p_tb[k]  = -0.5f * m * sg;       // constant term
        p_wh[k]  = 0.5f * ww;
        p_weh[k] = 0.5f * ww * er;
        denb += p_wh[k];
        numb += p_weh[k];
    }

    // ---- sensory params: lane c handles i = 3c, 3c+1, 3c+2 ----
    float s_na[3], s_tb[3], s_wh[3], s_weh[3], s_iw[3], s_ib[3];
    float s_base_d = 0.f, s_base_n = 0.f;
#pragma unroll
    for (int ii = 0; ii < 3; ii++) {
        int i = c * 3 + ii;
        float sg = ssigma[i * NU + u], m = smu[i * NU + u];
        float ww = swv[i * NU + u],    er = serev[i * NU + u];
        s_na[ii]  = 0.5f * sg;
        s_tb[ii]  = -0.5f * m * sg;
        s_wh[ii]  = 0.5f * ww;
        s_weh[ii] = 0.5f * ww * er;
        s_base_d += s_wh[ii];
        s_base_n += s_weh[ii];
        s_iw[ii] = in_w[i]; s_ib[ii] = in_b[i];
    }

    // ---- per-u constants ----
    const float cmt  = 6.0f * cm[u];     // cm / (elapsed/unfolds)
    const float gl   = gleak[u];
    const float glvl = gl * vleak[u];
    float ow = 0.f, ob = 0.f;
    if (u < NM) { ow = out_w[u]; ob = out_b[u]; }

    // ---- init state v = 0 ----
    if (tid < NU) vbuf[0][tid] = 0.f;
    __syncthreads();
    float vu = 0.f;   // register copy of v(u), redundant in both c-lanes

    const float* xb   = x   + (size_t)b * NT * NI;
    float*       outb = out + (size_t)b * NT * NM;

    // prefetch x for t=0
    float xv[3];
#pragma unroll
    for (int ii = 0; ii < 3; ii++) xv[ii] = xb[c * 3 + ii];

    for (int t = 0; t < NT; t++) {
        // ---- sensory sums (constant across unfolds) ----
        float ds = s_base_d, ns = s_base_n;
#pragma unroll
        for (int ii = 0; ii < 3; ii++) {
            float xi = fmaf(xv[ii], s_iw[ii], s_ib[ii]);
            float th = tanhf_(fmaf(xi, s_na[ii], s_tb[ii]));
            ds = fmaf(s_wh[ii],  th, ds);
            ns = fmaf(s_weh[ii], th, ns);
        }
        ns += __shfl_xor_sync(0xffffffffu, ns, 1);
        ds += __shfl_xor_sync(0xffffffffu, ds, 1);

        // ---- prefetch next timestep's x while unfolds run ----
        if (t + 1 < NT) {
#pragma unroll
            for (int ii = 0; ii < 3; ii++)
                xv[ii] = xb[(t + 1) * NI + c * 3 + ii];
        }

        // per-step constants folded once
        const float nn_c = glvl + ns;
        const float dd_c = cmt + gl + ds + EPSV;

#pragma unroll
        for (int s = 0; s < UNFOLDS; s++) {
            const int rb = s & 1;
            const float* vp = vbuf[rb];

            const float4* vp4 = (const float4*)(vp + c * 32);
            float vj[32];
#pragma unroll
            for (int q = 0; q < 8; q++) {
                float4 qq = vp4[q];
                vj[q * 4 + 0] = qq.x; vj[q * 4 + 1] = qq.y;
                vj[q * 4 + 2] = qq.z; vj[q * 4 + 3] = qq.w;
            }

            // two accumulator pairs for ILP; bases folded into pair 0
            float den0 = denb, den1 = 0.f, num0 = numb, num1 = 0.f;
#pragma unroll
            for (int k = 0; k < 32; k++) {
                float th = tanhf_(fmaf(vj[k], p_na[k], p_tb[k]));
                if (k & 1) {
                    den1 = fmaf(p_wh[k],  th, den1);
                    num1 = fmaf(p_weh[k], th, num1);
                } else {
                    den0 = fmaf(p_wh[k],  th, den0);
                    num0 = fmaf(p_weh[k], th, num0);
                }
            }
            float num = num0 + num1;
            float den = den0 + den1;
            num += __shfl_xor_sync(0xffffffffu, num, 1);
            den += __shfl_xor_sync(0xffffffffu, den, 1);

            // both lanes compute vn redundantly; vu stays in registers
            float nn = fmaf(cmt, vu, nn_c) + num;
            float dd = dd_c + den;
            float vn = nn * rcpf_(dd);
            vu = vn;
            if (c == 0) vbuf[rb ^ 1][u] = vn;
            __syncthreads();
        }

        // ---- output: first M motor neurons, affine ----
        if (c == 0 && u < NM) {
            outb[t * NM + u] = fmaf(vu, ow, ob);
        }
    }
}

extern "C" void kernel_launch(void* const* d_in, const int* in_sizes, int n_in,
                              void* d_out, int out_size) {
    (void)in_sizes; (void)n_in; (void)out_size;
    const float* xx     = (const float*)d_in[0];
    const float* gleak  = (const float*)d_in[1];
    const float* vleak  = (const float*)d_in[2];
    const float* cm     = (const float*)d_in[3];
    const float* sigma  = (const float*)d_in[4];
    const float* mu     = (const float*)d_in[5];
    const float* w      = (const float*)d_in[6];
    const float* erev   = (const float*)d_in[7];
    const float* ssig   = (const float*)d_in[8];
    const float* smu    = (const float*)d_in[9];
    const float* sw     = (const float*)d_in[10];
    const float* serev  = (const float*)d_in[11];
    const float* in_w   = (const float*)d_in[12];
    const float* in_b   = (const float*)d_in[13];
    const float* out_w  = (const float*)d_in[14];
    const float* out_b  = (const float*)d_in[15];
    float* out = (float*)d_out;

    ltc_seq_kernel<<<NB, 128>>>(xx, gleak, vleak, cm, sigma, mu, w, erev,
                                ssig, smu, sw, serev, in_w, in_b, out_w, out_b,
                                out);
}

// round 6
// speedup vs baseline: 1.5945x; 1.0017x over previous
#include <cuda_runtime.h>

// Problem constants (DgaRawSequence: B=256, T=8192, I=6, U=64, M=16)
#define NB 256
#define NT 8192
#define NI 6
#define NU 64
#define NM 16
#define UNFOLDS 6
#define EPSV 1e-8f

__device__ __forceinline__ float tanhf_(float v) {
    float y; asm("tanh.approx.f32 %0, %1;" : "=f"(y) : "f"(v)); return y;
}
__device__ __forceinline__ float rcpf_(float v) {
    float y; asm("rcp.approx.f32 %0, %1;" : "=f"(y) : "f"(v)); return y;
}

// sigmoid(z) = 0.5 + 0.5*tanh(z/2), 0.5's folded into weights.
// Block = 128 threads = 64 u-neurons x 2 j-chunks (32 presynaptic j each).
// tid = u*2 + c ; shfl.xor(1) reduces over c. One block per batch (grid=256,
// 2 blocks/SM co-resident). Blocks with bid >= 148 run a ~256-cycle
// deterministic delay chain before the scan so the two co-resident blocks
// (bid, bid+148) are ANTI-PHASED: each block's MUFU burst fills the other
// block's shfl/rcp/barrier tail instead of phase-locking with it.
__global__ void __launch_bounds__(128, 2) ltc_seq_kernel(
    const float* __restrict__ x,
    const float* __restrict__ gleak, const float* __restrict__ vleak,
    const float* __restrict__ cm,
    const float* __restrict__ sigma, const float* __restrict__ mu,
    const float* __restrict__ w,     const float* __restrict__ erev,
    const float* __restrict__ ssigma, const float* __restrict__ smu,
    const float* __restrict__ swv,    const float* __restrict__ serev,
    const float* __restrict__ in_w,  const float* __restrict__ in_b,
    const float* __restrict__ out_w, const float* __restrict__ out_b,
    float* __restrict__ out)
{
    const int tid = threadIdx.x;
    const int u   = tid >> 1;
    const int c   = tid & 1;
    const int b   = blockIdx.x;

    __shared__ __align__(16) float vbuf[2][NU];

    // ---- per-(j,u) recurrent params in registers, j = 32*c + k ----
    float p_na[32], p_tb[32], p_wh[32], p_weh[32];
    float denb = 0.f, numb = 0.f;   // sum of (w/2), (w*erev/2) bases
#pragma unroll
    for (int k = 0; k < 32; k++) {
        int j = c * 32 + k;
        float sg = sigma[j * NU + u];
        float m  = mu[j * NU + u];
        float ww = w[j * NU + u];
        float er = erev[j * NU + u];
        p_na[k]  = 0.5f * sg;            // multiplies v (z/2)
        p_tb[k]  = -0.5f * m * sg;       // constant term
        p_wh[k]  = 0.5f * ww;
        p_weh[k] = 0.5f * ww * er;
        denb += p_wh[k];
        numb += p_weh[k];
    }

    // ---- sensory params: lane c handles i = 3c, 3c+1, 3c+2 ----
    float s_na[3], s_tb[3], s_wh[3], s_weh[3], s_iw[3], s_ib[3];
    float s_base_d = 0.f, s_base_n = 0.f;
#pragma unroll
    for (int ii = 0; ii < 3; ii++) {
        int i = c * 3 + ii;
        float sg = ssigma[i * NU + u], m = smu[i * NU + u];
        float ww = swv[i * NU + u],    er = serev[i * NU + u];
        s_na[ii]  = 0.5f * sg;
        s_tb[ii]  = -0.5f * m * sg;
        s_wh[ii]  = 0.5f * ww;
        s_weh[ii] = 0.5f * ww * er;
        s_base_d += s_wh[ii];
        s_base_n += s_weh[ii];
        s_iw[ii] = in_w[i]; s_ib[ii] = in_b[i];
    }

    // ---- per-u constants ----
    const float cmt  = 6.0f * cm[u];     // cm / (elapsed/unfolds)
    const float gl   = gleak[u];
    const float glvl = gl * vleak[u];
    float ow = 0.f, ob = 0.f;
    if (u < NM) { ow = out_w[u]; ob = out_b[u]; }

    // ---- init state v = 0 ----
    if (tid < NU) vbuf[0][tid] = 0.f;

    // ---- anti-phase stagger: co-resident pairs are (b, b+148) ----
    if (b >= 148) {
        float d0 = 1.0f;
#pragma unroll
        for (int i = 0; i < 64; i++) {
            // 64 dependent 4-cyc FMAs ~ 256 cycles; volatile -> not eliminated.
            asm volatile("fma.rn.f32 %0, %0, 0f3F800001, 0f00000000;" : "+f"(d0));
        }
    }
    __syncthreads();
    float vu = 0.f;   // register copy of v(u), redundant in both c-lanes

    const float* xb   = x   + (size_t)b * NT * NI;
    float*       outb = out + (size_t)b * NT * NM;

    // prefetch x for t=0
    float xv[3];
#pragma unroll
    for (int ii = 0; ii < 3; ii++) xv[ii] = xb[c * 3 + ii];

    for (int t = 0; t < NT; t++) {
        // ---- sensory sums (constant across unfolds) ----
        float ds = s_base_d, ns = s_base_n;
#pragma unroll
        for (int ii = 0; ii < 3; ii++) {
            float xi = fmaf(xv[ii], s_iw[ii], s_ib[ii]);
            float th = tanhf_(fmaf(xi, s_na[ii], s_tb[ii]));
            ds = fmaf(s_wh[ii],  th, ds);
            ns = fmaf(s_weh[ii], th, ns);
        }
        ds += __shfl_xor_sync(0xffffffffu, ds, 1);
        ns += __shfl_xor_sync(0xffffffffu, ns, 1);

        // ---- prefetch next timestep's x while unfolds run ----
        if (t + 1 < NT) {
#pragma unroll
            for (int ii = 0; ii < 3; ii++)
                xv[ii] = xb[(t + 1) * NI + c * 3 + ii];
        }

        // per-step constants folded once
        const float nn_c = glvl + ns;
        const float dd_c = cmt + gl + ds + EPSV;

#pragma unroll
        for (int s = 0; s < UNFOLDS; s++) {
            const int rb = s & 1;
            const float* vp = vbuf[rb];

            const float4* vp4 = (const float4*)(vp + c * 32);
            float vj[32];
#pragma unroll
            for (int q = 0; q < 8; q++) {
                float4 qq = vp4[q];
                vj[q * 4 + 0] = qq.x; vj[q * 4 + 1] = qq.y;
                vj[q * 4 + 2] = qq.z; vj[q * 4 + 3] = qq.w;
            }

            // two accumulator pairs for ILP; bases folded into pair 0
            float den0 = denb, den1 = 0.f, num0 = numb, num1 = 0.f;
#pragma unroll
            for (int k = 0; k < 32; k++) {
                float th = tanhf_(fmaf(vj[k], p_na[k], p_tb[k]));
                if (k & 1) {
                    den1 = fmaf(p_wh[k],  th, den1);
                    num1 = fmaf(p_weh[k], th, num1);
                } else {
                    den0 = fmaf(p_wh[k],  th, den0);
                    num0 = fmaf(p_weh[k], th, num0);
                }
            }
            // den reduce FIRST so rcp (16cyc) overlaps num's shfl (26cyc)
            float den = den0 + den1;
            den += __shfl_xor_sync(0xffffffffu, den, 1);
            float num = num0 + num1;
            float r = rcpf_(dd_c + den);
            num += __shfl_xor_sync(0xffffffffu, num, 1);

            float nn = fmaf(cmt, vu, nn_c) + num;
            float vn = nn * r;
            vu = vn;
            if (c == 0) vbuf[rb ^ 1][u] = vn;
            __syncthreads();
        }

        // ---- output: first M motor neurons, affine ----
        if (c == 0 && u < NM) {
            outb[t * NM + u] = fmaf(vu, ow, ob);
        }
    }
}

extern "C" void kernel_launch(void* const* d_in, const int* in_sizes, int n_in,
                              void* d_out, int out_size) {
    (void)in_sizes; (void)n_in; (void)out_size;
    const float* xx     = (const float*)d_in[0];
    const float* gleak  = (const float*)d_in[1];
    const float* vleak  = (const float*)d_in[2];
    const float* cm     = (const float*)d_in[3];
    const float* sigma  = (const float*)d_in[4];
    const float* mu     = (const float*)d_in[5];
    const float* w      = (const float*)d_in[6];
    const float* erev   = (const float*)d_in[7];
    const float* ssig   = (const float*)d_in[8];
    const float* smu    = (const float*)d_in[9];
    const float* sw     = (const float*)d_in[10];
    const float* serev  = (const float*)d_in[11];
    const float* in_w   = (const float*)d_in[12];
    const float* in_b   = (const float*)d_in[13];
    const float* out_w  = (const float*)d_in[14];
    const float* out_b  = (const float*)d_in[15];
    float* out = (float*)d_out;

    ltc_seq_kernel<<<NB, 128>>>(xx, gleak, vleak, cm, sigma, mu, w, erev,
                                ssig, smu, sw, serev, in_w, in_b, out_w, out_b,
                                out);
}